// round 6
// baseline (speedup 1.0000x reference)
#include <cuda_runtime.h>
#include <cuda_fp16.h>

// AdditiveAttention: out = softmax_k( sum_h w_v[h]*tanh(qp[q,h]+kp[k,h]) ) @ V
// B=4, Q=K=512, H=256, fp32 in/out.
// proj (f32x2 GEMM -> f16) -> score (persistent, f16x2 tanh, f16 chain, f32 acc)
// -> softmax+PV (f32x2).

#define Bv 4
#define Qv 512
#define Kv 512
#define Hv 256
#define MROWS 2048
#define SGRID 456               // 3 blocks/SM x 152 SMs
#define NUNITS 2048             // (2048/8 q-tiles) x (512/64 k-tiles)

__device__ uint4 g_qph[MROWS * Hv / 8];   // projected q, f16
__device__ uint4 g_kph[MROWS * Hv / 8];   // projected k, f16
__device__ float g_sc[Bv * Qv * Kv];      // scores, 4MB

__device__ __forceinline__ __half2 tanh2_ap(__half2 x) {
    unsigned xi = *(unsigned*)&x, yi;
    asm("tanh.approx.f16x2 %0, %1;" : "=r"(yi) : "r"(xi));
    return *(__half2*)&yi;
}
__device__ __forceinline__ float ex2_ap(float x) {
    float y;
    asm("ex2.approx.f32 %0, %1;" : "=f"(y) : "f"(x));
    return y;
}
__device__ __forceinline__ void cp_async16(void* smem_dst, const void* gsrc) {
    unsigned s = (unsigned)__cvta_generic_to_shared(smem_dst);
    asm volatile("cp.async.cg.shared.global [%0], [%1], 16;\n" :: "r"(s), "l"(gsrc));
}
__device__ __forceinline__ void cp_commit() {
    asm volatile("cp.async.commit_group;\n");
}
__device__ __forceinline__ __half2 u2h(unsigned u) { return *(__half2*)&u; }

// ---- packed fp32x2 (Blackwell FFMA2 path) ----
__device__ __forceinline__ unsigned long long pk2(float x, float y) {
    unsigned long long r;
    asm("mov.b64 %0, {%1, %2};" : "=l"(r) : "f"(x), "f"(y));
    return r;
}
__device__ __forceinline__ void fma2(unsigned long long& d,
                                     unsigned long long a, unsigned long long b) {
    asm("fma.rn.f32x2 %0, %1, %2, %3;" : "=l"(d) : "l"(a), "l"(b), "l"(d));
}
__device__ __forceinline__ float2 upk2(unsigned long long v) {
    float2 f;
    asm("mov.b64 {%0, %1}, %2;" : "=f"(f.x), "=f"(f.y) : "l"(v));
    return f;
}

// ---------------------------------------------------------------------------
// Projection GEMM: C[m,o] = sum_h A[m,h]*W[o,h], f32x2 compute, f16 output.
// 64x64 tile, k-chunk 16, 4x4 microtile (as 4x2 f32x2), reg-prefetch dbuf.
// ---------------------------------------------------------------------------
__global__ __launch_bounds__(256) void proj_kernel(
    const float* __restrict__ A0, const float* __restrict__ W0, __half* __restrict__ C0,
    const float* __restrict__ A1, const float* __restrict__ W1, __half* __restrict__ C1)
{
    const float* A; const float* W; __half* C;
    if (blockIdx.z == 0) { A = A0; W = W0; C = C0; }
    else                 { A = A1; W = W1; C = C1; }

    __shared__ float As[16 * 68];
    __shared__ float Ws[16 * 68];

    const int tid = threadIdx.x;
    const int bm = blockIdx.y * 64;
    const int bn = blockIdx.x * 64;
    const int lr = tid >> 2;
    const int lc = (tid & 3) << 2;
    const int tm = (tid >> 4) << 2;
    const int tn = (tid & 15) << 2;

    const float4* A4 = (const float4*)A;
    const float4* W4 = (const float4*)W;
    const int arow = bm + lr;
    const int wrow = bn + lr;
    const int ccol = tid & 3;

    unsigned long long acc2[4][2];
#pragma unroll
    for (int i = 0; i < 4; i++) {
        acc2[i][0] = pk2(0.f, 0.f);
        acc2[i][1] = pk2(0.f, 0.f);
    }

    float4 a = A4[arow * 64 + ccol];
    float4 w = W4[wrow * 64 + ccol];

    for (int k0 = 0; k0 < Hv; k0 += 16) {
        As[(lc + 0) * 68 + lr] = a.x; As[(lc + 1) * 68 + lr] = a.y;
        As[(lc + 2) * 68 + lr] = a.z; As[(lc + 3) * 68 + lr] = a.w;
        Ws[(lc + 0) * 68 + lr] = w.x; Ws[(lc + 1) * 68 + lr] = w.y;
        Ws[(lc + 2) * 68 + lr] = w.z; Ws[(lc + 3) * 68 + lr] = w.w;
        __syncthreads();
        if (k0 + 16 < Hv) {
            a = A4[arow * 64 + ((k0 + 16) >> 2) + ccol];
            w = W4[wrow * 64 + ((k0 + 16) >> 2) + ccol];
        }
#pragma unroll
        for (int k = 0; k < 16; k++) {
            float4 av = *(const float4*)&As[k * 68 + tm];
            float4 wv = *(const float4*)&Ws[k * 68 + tn];
            unsigned long long w01 = pk2(wv.x, wv.y);
            unsigned long long w23 = pk2(wv.z, wv.w);
            float ar4[4] = {av.x, av.y, av.z, av.w};
#pragma unroll
            for (int i = 0; i < 4; i++) {
                unsigned long long ad = pk2(ar4[i], ar4[i]);
                fma2(acc2[i][0], ad, w01);
                fma2(acc2[i][1], ad, w23);
            }
        }
        __syncthreads();
    }
#pragma unroll
    for (int i = 0; i < 4; i++) {
        float2 lo = upk2(acc2[i][0]);
        float2 hi = upk2(acc2[i][1]);
        __half2 h0 = __floats2half2_rn(lo.x, lo.y);
        __half2 h1 = __floats2half2_rn(hi.x, hi.y);
        uint2 u; u.x = *(unsigned*)&h0; u.y = *(unsigned*)&h1;
        *(uint2*)&C[(bm + tm + i) * Hv + bn + tn] = u;
    }
}

// ---------------------------------------------------------------------------
// Score kernel (persistent): unit = 8 queries x 64 keys; 2048 units over
// grid 456. Cross-unit cp.async double buffering. f16 tanh + f16 weighted
// chain (8 links), f32 flush per 16-h chunk.
// ---------------------------------------------------------------------------
struct ScoreSmem {
    uint4 wvh[32];              // w_v as 256 halves
    uint4 qsh[2][256];
    uint4 kbh[2][2048];
};

__device__ __forceinline__ void score_prefetch(
    ScoreSmem* sm, const uint4* qp, const uint4* kp, int u, int p, int tid)
{
    const int qt = u >> 3;
    const int kt = u & 7;
    const int b = qt >> 6;
    const int qbase = (qt & 63) * 8;
    const uint4* qsrc = qp + (size_t)(b * Qv + qbase) * 32;
    cp_async16(&sm->qsh[p][tid], &qsrc[tid]);
    const uint4* ksrc = kp + (size_t)(b * Kv + kt * 64) * 32;
#pragma unroll
    for (int j = 0; j < 8; j++) {
        int idx = j * 256 + tid;
        int r = idx >> 5, c = idx & 31;
        cp_async16(&sm->kbh[p][r * 32 + (c ^ (r & 31))], &ksrc[r * 32 + c]);
    }
}

__global__ __launch_bounds__(256) void score_kernel(
    const uint4* __restrict__ qp, const uint4* __restrict__ kp,
    const float* __restrict__ wv_g, float* __restrict__ scores)
{
    extern __shared__ char smraw[];
    ScoreSmem* sm = (ScoreSmem*)smraw;

    const int tid  = threadIdx.x;
    const int lane = tid & 31;
    const int w    = tid >> 5;

    if (tid < 32) {
        float4 f0 = *(const float4*)&wv_g[tid * 8];
        float4 f1 = *(const float4*)&wv_g[tid * 8 + 4];
        __half2 h0 = __floats2half2_rn(f0.x, f0.y);
        __half2 h1 = __floats2half2_rn(f0.z, f0.w);
        __half2 h2 = __floats2half2_rn(f1.x, f1.y);
        __half2 h3 = __floats2half2_rn(f1.z, f1.w);
        uint4 u;
        u.x = *(unsigned*)&h0; u.y = *(unsigned*)&h1;
        u.z = *(unsigned*)&h2; u.w = *(unsigned*)&h3;
        sm->wvh[tid] = u;
    }

    const int qg   = w >> 1;
    const int rowk = (w & 1) * 32 + lane;
    const int q0   = qg * 2;

    int u = blockIdx.x;
    score_prefetch(sm, qp, kp, u, 0, tid);
    cp_commit();
    int p = 0;

    while (u < NUNITS) {
        int un = u + SGRID;
        if (un < NUNITS) {
            score_prefetch(sm, qp, kp, un, p ^ 1, tid);
            cp_commit();
            asm volatile("cp.async.wait_group 1;\n");
        } else {
            asm volatile("cp.async.wait_group 0;\n");
        }
        __syncthreads();

        const uint4* kb = sm->kbh[p];
        const uint4* qs = sm->qsh[p];
        float a00 = 0.f, a01 = 0.f, a10 = 0.f, a11 = 0.f;
#pragma unroll 4
        for (int h16 = 0; h16 < 16; h16++) {
            const int hA = 2 * h16, hB = 2 * h16 + 1;
            uint4 kuA = kb[rowk * 32 + (hA ^ lane)];
            uint4 kuB = kb[rowk * 32 + (hB ^ lane)];
            uint4 quA0 = qs[q0 * 32 + hA];
            uint4 quB0 = qs[q0 * 32 + hB];
            uint4 quA1 = qs[q0 * 32 + 32 + hA];
            uint4 quB1 = qs[q0 * 32 + 32 + hB];
            uint4 wuA = sm->wvh[hA];
            uint4 wuB = sm->wvh[hB];
            __half2 kA0 = u2h(kuA.x), kA1 = u2h(kuA.y), kA2 = u2h(kuA.z), kA3 = u2h(kuA.w);
            __half2 kB0 = u2h(kuB.x), kB1 = u2h(kuB.y), kB2 = u2h(kuB.z), kB3 = u2h(kuB.w);
            __half2 wA0 = u2h(wuA.x), wA1 = u2h(wuA.y), wA2 = u2h(wuA.z), wA3 = u2h(wuA.w);
            __half2 wB0 = u2h(wuB.x), wB1 = u2h(wuB.y), wB2 = u2h(wuB.z), wB3 = u2h(wuB.w);
            __half2 s0;
            s0 = __hmul2(tanh2_ap(__hadd2(u2h(quA0.x), kA0)), wA0);
            s0 = __hfma2(tanh2_ap(__hadd2(u2h(quA0.y), kA1)), wA1, s0);
            s0 = __hfma2(tanh2_ap(__hadd2(u2h(quA0.z), kA2)), wA2, s0);
            s0 = __hfma2(tanh2_ap(__hadd2(u2h(quA0.w), kA3)), wA3, s0);
            s0 = __hfma2(tanh2_ap(__hadd2(u2h(quB0.x), kB0)), wB0, s0);
            s0 = __hfma2(tanh2_ap(__hadd2(u2h(quB0.y), kB1)), wB1, s0);
            s0 = __hfma2(tanh2_ap(__hadd2(u2h(quB0.z), kB2)), wB2, s0);
            s0 = __hfma2(tanh2_ap(__hadd2(u2h(quB0.w), kB3)), wB3, s0);
            float2 f0 = __half22float2(s0);
            a00 += f0.x; a01 += f0.y;
            __half2 s1;
            s1 = __hmul2(tanh2_ap(__hadd2(u2h(quA1.x), kA0)), wA0);
            s1 = __hfma2(tanh2_ap(__hadd2(u2h(quA1.y), kA1)), wA1, s1);
            s1 = __hfma2(tanh2_ap(__hadd2(u2h(quA1.z), kA2)), wA2, s1);
            s1 = __hfma2(tanh2_ap(__hadd2(u2h(quA1.w), kA3)), wA3, s1);
            s1 = __hfma2(tanh2_ap(__hadd2(u2h(quB1.x), kB0)), wB0, s1);
            s1 = __hfma2(tanh2_ap(__hadd2(u2h(quB1.y), kB1)), wB1, s1);
            s1 = __hfma2(tanh2_ap(__hadd2(u2h(quB1.z), kB2)), wB2, s1);
            s1 = __hfma2(tanh2_ap(__hadd2(u2h(quB1.w), kB3)), wB3, s1);
            float2 f1 = __half22float2(s1);
            a10 += f1.x; a11 += f1.y;
        }
        {
            const int qt = u >> 3;
            const int kt = u & 7;
            const int b = qt >> 6;
            const int qbase = (qt & 63) * 8;
            const int key = kt * 64 + rowk;
            scores[(size_t)(b * Qv + qbase + q0) * Kv + key]     = a00 + a01;
            scores[(size_t)(b * Qv + qbase + q0 + 1) * Kv + key] = a10 + a11;
        }
        __syncthreads();
        u = un; p ^= 1;
    }
}

// ---------------------------------------------------------------------------
// Softmax + PV. Grid 128: block = 16 queries, 512 threads (16 warps).
// Softmax: warp w -> query w. PV (f32x2): warp w -> qgroup (w&7)*2..+2,
// dim half (w>>3)*128, lane: 4 dims. V tiles (32 keys) double-buffered.
// smem: ps f32[16][512] 32KB | vb f32[2][32][256] 64KB = 96KB
// ---------------------------------------------------------------------------
__global__ __launch_bounds__(512) void softmax_pv_kernel(
    const float* __restrict__ scores, const float* __restrict__ V,
    float* __restrict__ out)
{
    extern __shared__ float smB[];
    float* ps = smB;               // [16][512]
    float* vb = smB + 16 * Kv;     // [2][32][256]

    const int tid  = threadIdx.x;
    const int lane = tid & 31;
    const int w    = tid >> 5;
    const int b     = blockIdx.x >> 5;
    const int qbase = (blockIdx.x & 31) * 16;

    const float4* vsrc_base = (const float4*)V + (size_t)(b * Kv) * 64;

    // prefetch V tile 0 (32 keys x 256 dims)
#pragma unroll
    for (int j = 0; j < 4; j++) {
        int idx = j * 512 + tid;
        int r = idx >> 6, c = idx & 63;
        cp_async16(&vb[r * Hv + c * 4], &vsrc_base[r * 64 + c]);
    }
    cp_commit();

    // ---- softmax: warp w handles query qbase+w ----
    {
        const float LOG2E = 1.4426950408889634f;
        const float* src = &scores[(size_t)(b * Qv + qbase + w) * Kv];
        float4 xv[4];
        float mx = -1e30f;
#pragma unroll
        for (int j = 0; j < 4; j++) {
            xv[j] = *(const float4*)&src[j * 128 + lane * 4];
            mx = fmaxf(mx, fmaxf(fmaxf(xv[j].x, xv[j].y), fmaxf(xv[j].z, xv[j].w)));
        }
#pragma unroll
        for (int off = 16; off > 0; off >>= 1)
            mx = fmaxf(mx, __shfl_xor_sync(0xffffffffu, mx, off));
        float s = 0.f;
#pragma unroll
        for (int j = 0; j < 4; j++) {
            xv[j].x = ex2_ap((xv[j].x - mx) * LOG2E);
            xv[j].y = ex2_ap((xv[j].y - mx) * LOG2E);
            xv[j].z = ex2_ap((xv[j].z - mx) * LOG2E);
            xv[j].w = ex2_ap((xv[j].w - mx) * LOG2E);
            s += xv[j].x + xv[j].y + xv[j].z + xv[j].w;
        }
#pragma unroll
        for (int off = 16; off > 0; off >>= 1)
            s += __shfl_xor_sync(0xffffffffu, s, off);
        float inv = __fdividef(1.f, s);
#pragma unroll
        for (int j = 0; j < 4; j++) {
            xv[j].x *= inv; xv[j].y *= inv; xv[j].z *= inv; xv[j].w *= inv;
            *(float4*)&ps[w * Kv + j * 128 + lane * 4] = xv[j];
        }
    }

    // ---- PV (f32x2) ----
    const int qg  = w & 7;                    // 2 queries: qbase + qg*2 + {0,1}
    const int dof = (w >> 3) * 128 + lane * 4; // 4 dims per lane

    unsigned long long acc2[2][2];
    acc2[0][0] = pk2(0.f, 0.f); acc2[0][1] = pk2(0.f, 0.f);
    acc2[1][0] = pk2(0.f, 0.f); acc2[1][1] = pk2(0.f, 0.f);

    for (int kt = 0; kt < 16; kt++) {
        if (kt < 15) {
            float* dst = vb + ((kt + 1) & 1) * 32 * Hv;
            const float4* src = vsrc_base + (size_t)(kt + 1) * 32 * 64;
#pragma unroll
            for (int j = 0; j < 4; j++) {
                int idx = j * 512 + tid;
                int r = idx >> 6, c = idx & 63;
                cp_async16(&dst[r * Hv + c * 4], &src[r * 64 + c]);
            }
            cp_commit();
            asm volatile("cp.async.wait_group 1;\n");
        } else {
            asm volatile("cp.async.wait_group 0;\n");
        }
        __syncthreads();

        const float* vt = vb + (kt & 1) * 32 * Hv;
#pragma unroll 2
        for (int kk4 = 0; kk4 < 8; kk4++) {
            float4 p0 = *(const float4*)&ps[(qg * 2 + 0) * Kv + kt * 32 + kk4 * 4];
            float4 p1 = *(const float4*)&ps[(qg * 2 + 1) * Kv + kt * 32 + kk4 * 4];
            float p0a[4] = {p0.x, p0.y, p0.z, p0.w};
            float p1a[4] = {p1.x, p1.y, p1.z, p1.w};
#pragma unroll
            for (int kk = 0; kk < 4; kk++) {
                float4 v = *(const float4*)&vt[(kk4 * 4 + kk) * Hv + dof];
                unsigned long long vlo = pk2(v.x, v.y);
                unsigned long long vhi = pk2(v.z, v.w);
                unsigned long long pd0 = pk2(p0a[kk], p0a[kk]);
                unsigned long long pd1 = pk2(p1a[kk], p1a[kk]);
                fma2(acc2[0][0], pd0, vlo);
                fma2(acc2[0][1], pd0, vhi);
                fma2(acc2[1][0], pd1, vlo);
                fma2(acc2[1][1], pd1, vhi);
            }
        }
        __syncthreads();
    }
#pragma unroll
    for (int j = 0; j < 2; j++) {
        float2 lo = upk2(acc2[j][0]);
        float2 hi = upk2(acc2[j][1]);
        float4 o = make_float4(lo.x, lo.y, hi.x, hi.y);
        *(float4*)&out[(size_t)(b * Qv + qbase + qg * 2 + j) * Hv + dof] = o;
    }
}

extern "C" void kernel_launch(void* const* d_in, const int* in_sizes, int n_in,
                              void* d_out, int out_size)
{
    const float* queries = (const float*)d_in[0];
    const float* keys    = (const float*)d_in[1];
    const float* values  = (const float*)d_in[2];
    const float* W_q     = (const float*)d_in[3];
    const float* W_k     = (const float*)d_in[4];
    const float* w_v     = (const float*)d_in[5];
    float* out = (float*)d_out;

    uint4 *qph, *kph; float* sc;
    cudaGetSymbolAddress((void**)&qph, g_qph);
    cudaGetSymbolAddress((void**)&kph, g_kph);
    cudaGetSymbolAddress((void**)&sc, g_sc);

    proj_kernel<<<dim3(4, 32, 2), 256>>>(queries, W_q, (__half*)qph,
                                         keys, W_k, (__half*)kph);

    const int smA = (int)sizeof(ScoreSmem);   // 74240 B
    cudaFuncSetAttribute(score_kernel, cudaFuncAttributeMaxDynamicSharedMemorySize, smA);
    score_kernel<<<SGRID, 256, smA>>>(qph, kph, w_v, sc);

    const int smB = (16 * Kv + 2 * 32 * Hv) * (int)sizeof(float);  // 98304 B
    cudaFuncSetAttribute(softmax_pv_kernel, cudaFuncAttributeMaxDynamicSharedMemorySize, smB);
    softmax_pv_kernel<<<128, 512, smB>>>(sc, values, out);
}